// round 9
// baseline (speedup 1.0000x reference)
#include <cuda_runtime.h>
#include <cuda_fp16.h>

// actor_53781580480512 R9: R8 body, BTILE=64 (grid 64x64 = 4096 CTAs)
// to kill wave quantization (3.46 waves -> 6.92 waves, tail 13.5% -> 1%).
//   B=4096, Z=64, P=4096, H=4

#define ZDIM 64
#define PDIM 4096
#define BTILE 64

__device__ __forceinline__ __half2 tanh2(__half2 v) {
    unsigned vi = *reinterpret_cast<unsigned*>(&v), ri;
    asm("tanh.approx.f16x2 %0, %1;" : "=r"(ri) : "r"(vi));
    return *reinterpret_cast<__half2*>(&ri);
}

__global__ __launch_bounds__(256, 4)
void actor_mlp_kernel(
    const float* __restrict__ x,
    const float* __restrict__ W1, const float* __restrict__ b1,
    const float* __restrict__ g1, const float* __restrict__ be1,
    const float* __restrict__ W2, const float* __restrict__ b2,
    const float* __restrict__ g2, const float* __restrict__ be2,
    const float* __restrict__ W3, const float* __restrict__ b3,
    float* __restrict__ out, int B)
{
    const int zp = threadIdx.x & 63;        // 0..63
    const int bl = threadIdx.x >> 6;        // 0..3
    const int z  = blockIdx.x;              // 0..63
    const int b0 = blockIdx.y * BTILE;
    const int p  = z * ZDIM + zp;

    // ================= prologue: load + fold (once per 16 b) ================
    __half2 w1h[8], bb1h[4];
    {
        float4 a = __ldg((const float4*)&W1[p * 8]);
        float4 c = __ldg((const float4*)&W1[p * 8 + 4]);
        w1h[0]=__float2half2_rn(a.x); w1h[1]=__float2half2_rn(a.y);
        w1h[2]=__float2half2_rn(a.z); w1h[3]=__float2half2_rn(a.w);
        w1h[4]=__float2half2_rn(c.x); w1h[5]=__float2half2_rn(c.y);
        w1h[6]=__float2half2_rn(c.z); w1h[7]=__float2half2_rn(c.w);
        float4 bv = __ldg((const float4*)&b1[p * 4]);
        bb1h[0]=__float2half2_rn(bv.x); bb1h[1]=__float2half2_rn(bv.y);
        bb1h[2]=__float2half2_rn(bv.z); bb1h[3]=__float2half2_rn(bv.w);
    }

    __half2 w2h[16], bb2h[4], w3h[4], bb3h;
    {
        float4 g1v  = __ldg((const float4*)&g1 [p * 4]);
        float4 be1v = __ldg((const float4*)&be1[p * 4]);
        float gg1[4]  = {2.0f*g1v.x, 2.0f*g1v.y, 2.0f*g1v.z, 2.0f*g1v.w};
        float bbe1[4] = {be1v.x, be1v.y, be1v.z, be1v.w};
        float4 b2v = __ldg((const float4*)&b2[p * 4]);
        float b2f[4] = {b2v.x, b2v.y, b2v.z, b2v.w};
#pragma unroll
        for (int i = 0; i < 4; i++) {
            float4 wr = __ldg((const float4*)&W2[p * 16 + i * 4]);
            float wrow[4] = {wr.x, wr.y, wr.z, wr.w};
#pragma unroll
            for (int j = 0; j < 4; j++) {
                w2h[i * 4 + j] = __float2half2_rn(gg1[i] * wrow[j]);
                b2f[j] = fmaf(bbe1[i], wrow[j], b2f[j]);
            }
        }
#pragma unroll
        for (int j = 0; j < 4; j++) bb2h[j] = __float2half2_rn(b2f[j]);

        float4 g2v  = __ldg((const float4*)&g2 [p * 4]);
        float4 be2v = __ldg((const float4*)&be2[p * 4]);
        float4 w3v  = __ldg((const float4*)&W3 [p * 4]);
        // 2x (rsqrt fold) * 0.5 (sigmoid fold) = 1x
        w3h[0] = __float2half2_rn(g2v.x * w3v.x);
        w3h[1] = __float2half2_rn(g2v.y * w3v.y);
        w3h[2] = __float2half2_rn(g2v.z * w3v.z);
        w3h[3] = __float2half2_rn(g2v.w * w3v.w);
        float b3f = __ldg(&b3[p]);
        b3f = fmaf(be2v.x, w3v.x, b3f);
        b3f = fmaf(be2v.y, w3v.y, b3f);
        b3f = fmaf(be2v.z, w3v.z, b3f);
        b3f = fmaf(be2v.w, w3v.w, b3f);
        bb3h = __float2half2_rn(0.5f * b3f);
    }

    const __half2 cNQ   = __float2half2_rn(-0.25f);
    const __half2 cEps4 = __float2half2_rn(4e-5f);
    const __half2 cH    = __float2half2_rn(0.5f);

    const float* xpa = x + (b0 + 4 * bl) * ZDIM + z;
    const float* xpc = x + (b0 + 4 * bl) * ZDIM + zp;
    float*       opt = out + (b0 + 4 * bl) * PDIM + p;

    // ============ main loop: 4 b-elements / thread / iteration ==============
#pragma unroll 1
    for (int it = 0; it < BTILE / 16; it++) {        // 4 iterations
        float xa[4], xc[4];
#pragma unroll
        for (int u = 0; u < 4; u++) {
            xa[u] = __ldg(xpa + u * ZDIM);           // warp-uniform, L1-hot
            xc[u] = __ldg(xpc + u * ZDIM);           // coalesced
        }
        xpa += 16 * ZDIM; xpc += 16 * ZDIM;

        float o[4];
#pragma unroll
        for (int u = 0; u < 2; u++) {                // 2 independent chains
            __half2 xa2 = __floats2half2_rn(xa[2*u], xa[2*u+1]);
            __half2 xc2 = __floats2half2_rn(xc[2*u], xc[2*u+1]);

            // layer 1 + tanh
            __half2 h[4];
#pragma unroll
            for (int j = 0; j < 4; j++)
                h[j] = tanh2(__hfma2(xa2, w1h[j],
                             __hfma2(xc2, w1h[4 + j], bb1h[j])));

            // LN1: balanced var tree, eps in leaf; affine + 2x folded into w2h
            __half2 sum = __hadd2(__hadd2(h[0], h[1]), __hadd2(h[2], h[3]));
            __half2 nm  = __hmul2(sum, cNQ);
            __half2 d0 = __hadd2(h[0], nm), d1 = __hadd2(h[1], nm);
            __half2 d2 = __hadd2(h[2], nm), d3 = __hadd2(h[3], nm);
            __half2 va = __hfma2(d0, d0, __hmul2(d1, d1));
            __half2 vb = __hfma2(d2, d2, __hfma2(d3, d3, cEps4));
            __half2 r  = h2rsqrt(__hadd2(va, vb));

            // layer 2 + tanh
            __half2 k[4];
#pragma unroll
            for (int j = 0; j < 4; j++) {
                __half2 dot = __hmul2(d0, w2h[j]);
                dot = __hfma2(d1, w2h[4 + j], dot);
                dot = __hfma2(d2, w2h[8 + j], dot);
                dot = __hfma2(d3, w2h[12 + j], dot);
                k[j] = tanh2(__hfma2(r, dot, bb2h[j]));
            }

            // LN2
            __half2 sum2 = __hadd2(__hadd2(k[0], k[1]), __hadd2(k[2], k[3]));
            __half2 nm2  = __hmul2(sum2, cNQ);
            __half2 e0 = __hadd2(k[0], nm2), e1 = __hadd2(k[1], nm2);
            __half2 e2 = __hadd2(k[2], nm2), e3 = __hadd2(k[3], nm2);
            __half2 wa = __hfma2(e0, e0, __hmul2(e1, e1));
            __half2 wb = __hfma2(e2, e2, __hfma2(e3, e3, cEps4));
            __half2 r2 = h2rsqrt(__hadd2(wa, wb));

            // layer 3 + sigmoid (0.5 pre-folded): o = 0.5*tanh(pre) + 0.5
            __half2 dot3 = __hmul2(e0, w3h[0]);
            dot3 = __hfma2(e1, w3h[1], dot3);
            dot3 = __hfma2(e2, w3h[2], dot3);
            dot3 = __hfma2(e3, w3h[3], dot3);
            __half2 pre = __hfma2(r2, dot3, bb3h);
            __half2 og  = __hfma2(tanh2(pre), cH, cH);

            float2 of = __half22float2(og);
            o[2*u] = of.x; o[2*u+1] = of.y;
        }

#pragma unroll
        for (int u = 0; u < 4; u++)
            opt[u * PDIM] = o[u];
        opt += 16 * PDIM;
    }
}

extern "C" void kernel_launch(void* const* d_in, const int* in_sizes, int n_in,
                              void* d_out, int out_size)
{
    const float* x   = (const float*)d_in[0];
    const float* W1  = (const float*)d_in[1];
    const float* b1  = (const float*)d_in[2];
    const float* g1  = (const float*)d_in[3];
    const float* be1 = (const float*)d_in[4];
    const float* W2  = (const float*)d_in[5];
    const float* b2  = (const float*)d_in[6];
    const float* g2  = (const float*)d_in[7];
    const float* be2 = (const float*)d_in[8];
    const float* W3  = (const float*)d_in[9];
    const float* b3  = (const float*)d_in[10];
    float* out = (float*)d_out;

    int B = in_sizes[0] / ZDIM;
    dim3 grid(ZDIM, (B + BTILE - 1) / BTILE);   // 64 x 64 = 4096 CTAs
    actor_mlp_kernel<<<grid, 256>>>(x, W1, b1, g1, be1, W2, b2, g2, be2,
                                    W3, b3, out, B);
}

// round 10
// speedup vs baseline: 1.0071x; 1.0071x over previous
#include <cuda_runtime.h>
#include <cuda_fp16.h>

// actor_53781580480512 R10: smem x-tile (transposed, pre-halved) kills all
// in-loop LDGs; body = R8/R9 (half2, ILP=2 chains, all folds, 4 CTAs/SM).
//   B=4096, Z=64, P=4096, H=4, BTILE=64

#define ZDIM 64
#define PDIM 4096
#define BTILE 64
#define SROW 66            // 64 + 2 halves pad -> 33-word row stride

__device__ __forceinline__ __half2 tanh2(__half2 v) {
    unsigned vi = *reinterpret_cast<unsigned*>(&v), ri;
    asm("tanh.approx.f16x2 %0, %1;" : "=r"(ri) : "r"(vi));
    return *reinterpret_cast<__half2*>(&ri);
}

__global__ __launch_bounds__(256, 4)
void actor_mlp_kernel(
    const float* __restrict__ x,
    const float* __restrict__ W1, const float* __restrict__ b1,
    const float* __restrict__ g1, const float* __restrict__ be1,
    const float* __restrict__ W2, const float* __restrict__ b2,
    const float* __restrict__ g2, const float* __restrict__ be2,
    const float* __restrict__ W3, const float* __restrict__ b3,
    float* __restrict__ out, int B)
{
    __shared__ __half sx[ZDIM][SROW];       // sx[zp][b] : transposed x tile

    const int zp = threadIdx.x & 63;        // 0..63
    const int bl = threadIdx.x >> 6;        // 0..3
    const int z  = blockIdx.x;              // 0..63
    const int b0 = blockIdx.y * BTILE;
    const int p  = z * ZDIM + zp;

    // ---- cooperative x-tile load: 64 b x 64 z, f32 -> half, transposed ----
    {
        const int bi   = threadIdx.x >> 2;          // 0..63 (b row)
        const int quad = threadIdx.x & 3;           // 0..3  (16-z chunk)
        const float4* src = (const float4*)&x[(b0 + bi) * ZDIM + quad * 16];
#pragma unroll
        for (int q = 0; q < 4; q++) {
            float4 v = __ldg(src + q);
            int zj = quad * 16 + q * 4;
            sx[zj + 0][bi] = __float2half_rn(v.x);
            sx[zj + 1][bi] = __float2half_rn(v.y);
            sx[zj + 2][bi] = __float2half_rn(v.z);
            sx[zj + 3][bi] = __float2half_rn(v.w);
        }
    }

    // ================= prologue: load + fold (once per 16 b) ================
    __half2 w1h[8], bb1h[4];
    {
        float4 a = __ldg((const float4*)&W1[p * 8]);
        float4 c = __ldg((const float4*)&W1[p * 8 + 4]);
        w1h[0]=__float2half2_rn(a.x); w1h[1]=__float2half2_rn(a.y);
        w1h[2]=__float2half2_rn(a.z); w1h[3]=__float2half2_rn(a.w);
        w1h[4]=__float2half2_rn(c.x); w1h[5]=__float2half2_rn(c.y);
        w1h[6]=__float2half2_rn(c.z); w1h[7]=__float2half2_rn(c.w);
        float4 bv = __ldg((const float4*)&b1[p * 4]);
        bb1h[0]=__float2half2_rn(bv.x); bb1h[1]=__float2half2_rn(bv.y);
        bb1h[2]=__float2half2_rn(bv.z); bb1h[3]=__float2half2_rn(bv.w);
    }

    __half2 w2h[16], bb2h[4], w3h[4], bb3h;
    {
        float4 g1v  = __ldg((const float4*)&g1 [p * 4]);
        float4 be1v = __ldg((const float4*)&be1[p * 4]);
        float gg1[4]  = {2.0f*g1v.x, 2.0f*g1v.y, 2.0f*g1v.z, 2.0f*g1v.w};
        float bbe1[4] = {be1v.x, be1v.y, be1v.z, be1v.w};
        float4 b2v = __ldg((const float4*)&b2[p * 4]);
        float b2f[4] = {b2v.x, b2v.y, b2v.z, b2v.w};
#pragma unroll
        for (int i = 0; i < 4; i++) {
            float4 wr = __ldg((const float4*)&W2[p * 16 + i * 4]);
            float wrow[4] = {wr.x, wr.y, wr.z, wr.w};
#pragma unroll
            for (int j = 0; j < 4; j++) {
                w2h[i * 4 + j] = __float2half2_rn(gg1[i] * wrow[j]);
                b2f[j] = fmaf(bbe1[i], wrow[j], b2f[j]);
            }
        }
#pragma unroll
        for (int j = 0; j < 4; j++) bb2h[j] = __float2half2_rn(b2f[j]);

        float4 g2v  = __ldg((const float4*)&g2 [p * 4]);
        float4 be2v = __ldg((const float4*)&be2[p * 4]);
        float4 w3v  = __ldg((const float4*)&W3 [p * 4]);
        // 2x (rsqrt fold) * 0.5 (sigmoid fold) = 1x
        w3h[0] = __float2half2_rn(g2v.x * w3v.x);
        w3h[1] = __float2half2_rn(g2v.y * w3v.y);
        w3h[2] = __float2half2_rn(g2v.z * w3v.z);
        w3h[3] = __float2half2_rn(g2v.w * w3v.w);
        float b3f = __ldg(&b3[p]);
        b3f = fmaf(be2v.x, w3v.x, b3f);
        b3f = fmaf(be2v.y, w3v.y, b3f);
        b3f = fmaf(be2v.z, w3v.z, b3f);
        b3f = fmaf(be2v.w, w3v.w, b3f);
        bb3h = __float2half2_rn(0.5f * b3f);
    }

    const __half2 cNQ   = __float2half2_rn(-0.25f);
    const __half2 cEps4 = __float2half2_rn(4e-5f);
    const __half2 cH    = __float2half2_rn(0.5f);

    __syncthreads();                        // x tile ready

    float* opt = out + (b0 + 4 * bl) * PDIM + p;

    // ============ main loop: 4 b-elements / thread / iteration ==============
#pragma unroll 1
    for (int it = 0; it < BTILE / 16; it++) {        // 4 iterations
        const int bb = 4 * bl + 16 * it;

        float o[4];
#pragma unroll
        for (int u = 0; u < 2; u++) {                // 2 independent chains
            // packed (b, b+1) inputs straight from smem (LDS.32 each)
            __half2 xa2 = *(const __half2*)&sx[z][bb + 2 * u];   // broadcast
            __half2 xc2 = *(const __half2*)&sx[zp][bb + 2 * u];  // conflict-free

            // layer 1 + tanh
            __half2 h[4];
#pragma unroll
            for (int j = 0; j < 4; j++)
                h[j] = tanh2(__hfma2(xa2, w1h[j],
                             __hfma2(xc2, w1h[4 + j], bb1h[j])));

            // LN1: balanced var tree, eps in leaf; affine + 2x folded into w2h
            __half2 sum = __hadd2(__hadd2(h[0], h[1]), __hadd2(h[2], h[3]));
            __half2 nm  = __hmul2(sum, cNQ);
            __half2 d0 = __hadd2(h[0], nm), d1 = __hadd2(h[1], nm);
            __half2 d2 = __hadd2(h[2], nm), d3 = __hadd2(h[3], nm);
            __half2 va = __hfma2(d0, d0, __hmul2(d1, d1));
            __half2 vb = __hfma2(d2, d2, __hfma2(d3, d3, cEps4));
            __half2 r  = h2rsqrt(__hadd2(va, vb));

            // layer 2 + tanh
            __half2 k[4];
#pragma unroll
            for (int j = 0; j < 4; j++) {
                __half2 dot = __hmul2(d0, w2h[j]);
                dot = __hfma2(d1, w2h[4 + j], dot);
                dot = __hfma2(d2, w2h[8 + j], dot);
                dot = __hfma2(d3, w2h[12 + j], dot);
                k[j] = tanh2(__hfma2(r, dot, bb2h[j]));
            }

            // LN2
            __half2 sum2 = __hadd2(__hadd2(k[0], k[1]), __hadd2(k[2], k[3]));
            __half2 nm2  = __hmul2(sum2, cNQ);
            __half2 e0 = __hadd2(k[0], nm2), e1 = __hadd2(k[1], nm2);
            __half2 e2 = __hadd2(k[2], nm2), e3 = __hadd2(k[3], nm2);
            __half2 wa = __hfma2(e0, e0, __hmul2(e1, e1));
            __half2 wb = __hfma2(e2, e2, __hfma2(e3, e3, cEps4));
            __half2 r2 = h2rsqrt(__hadd2(wa, wb));

            // layer 3 + sigmoid (0.5 pre-folded): o = 0.5*tanh(pre) + 0.5
            __half2 dot3 = __hmul2(e0, w3h[0]);
            dot3 = __hfma2(e1, w3h[1], dot3);
            dot3 = __hfma2(e2, w3h[2], dot3);
            dot3 = __hfma2(e3, w3h[3], dot3);
            __half2 pre = __hfma2(r2, dot3, bb3h);
            __half2 og  = __hfma2(tanh2(pre), cH, cH);

            float2 of = __half22float2(og);
            o[2*u] = of.x; o[2*u+1] = of.y;
        }

#pragma unroll
        for (int u = 0; u < 4; u++)
            opt[u * PDIM] = o[u];
        opt += 16 * PDIM;
    }
}

extern "C" void kernel_launch(void* const* d_in, const int* in_sizes, int n_in,
                              void* d_out, int out_size)
{
    const float* x   = (const float*)d_in[0];
    const float* W1  = (const float*)d_in[1];
    const float* b1  = (const float*)d_in[2];
    const float* g1  = (const float*)d_in[3];
    const float* be1 = (const float*)d_in[4];
    const float* W2  = (const float*)d_in[5];
    const float* b2  = (const float*)d_in[6];
    const float* g2  = (const float*)d_in[7];
    const float* be2 = (const float*)d_in[8];
    const float* W3  = (const float*)d_in[9];
    const float* b3  = (const float*)d_in[10];
    float* out = (float*)d_out;

    int B = in_sizes[0] / ZDIM;
    dim3 grid(ZDIM, (B + BTILE - 1) / BTILE);   // 64 x 64 = 4096 CTAs
    actor_mlp_kernel<<<grid, 256>>>(x, W1, b1, g1, be1, W2, b2, g2, be2,
                                    W3, b3, out, B);
}